// round 13
// baseline (speedup 1.0000x reference)
#include <cuda_runtime.h>
#include <cstdint>
#include <math.h>

// ---------------------------------------------------------------------------
// Shapes
//   x0: [2, 256, 32^3]   -> 512 channel-slices of 32768 elems ( 8192 f4)
//   x1: [2, 128, 64^3]   -> 256 channel-slices of 262144 elems (65536 f = 16384 f4)
//   x2: [2,  64, 128^3]  -> 128 channel-slices of 2097152 elems (524288 f4)
// Grid = 4736 blocks = EXACTLY 4 waves at 8 CTA/SM x 148 SMs (1184 slots).
//   x2: 25 chunks/slice (24 x 20972 f4 + 1 x 20960 f4) -> 3200 @ g_part[0]
//   x1:  4 chunks/slice (16384 f4)                     -> 1024 @ g_part[3200]
//   x0:  1 chunk /slice ( 8192 f4)                     ->  512 @ g_part[4224]
// gap_reduce fires PDL completion at entry; epilogue launched with PSS.
// ---------------------------------------------------------------------------

__device__ __align__(16) float g_part[4736];

__global__ __launch_bounds__(256) void gap_reduce(
    const float* __restrict__ x0,
    const float* __restrict__ x1,
    const float* __restrict__ x2)
{
#if __CUDA_ARCH__ >= 900
    cudaTriggerProgrammaticLaunchCompletion();
#endif
    int bid = blockIdx.x;

    const float4* src;
    int nvec;
    if (bid < 3200) {                      // x2: 25 chunks per 524288-f4 slice
        int slice = bid / 25;
        int j     = bid - slice * 25;
        int start = j * 20972;
        int end   = (j == 24) ? 524288 : start + 20972;
        src  = reinterpret_cast<const float4*>(x2) + (size_t)slice * 524288 + start;
        nvec = end - start;
    } else if (bid < 4224) {               // x1: 16384-f4 chunks
        src  = reinterpret_cast<const float4*>(x1) + (size_t)(bid - 3200) * 16384;
        nvec = 16384;
    } else {                               // x0: 8192-f4 chunks
        src  = reinterpret_cast<const float4*>(x0) + (size_t)(bid - 4224) * 8192;
        nvec = 8192;
    }

    float s = 0.f;
    #pragma unroll 4
    for (int i = threadIdx.x; i < nvec; i += 256) {
        float4 a = __ldcs(src + i);          // streaming: evict-first in L2
        s += (a.x + a.y) + (a.z + a.w);
    }

    __shared__ float sbuf[8];
    #pragma unroll
    for (int o = 16; o; o >>= 1) s += __shfl_down_sync(0xffffffffu, s, o);
    if ((threadIdx.x & 31) == 0) sbuf[threadIdx.x >> 5] = s;
    __syncthreads();
    if (threadIdx.x < 8) {
        s = sbuf[threadIdx.x];
        #pragma unroll
        for (int o = 4; o; o >>= 1) s += __shfl_down_sync(0x000000ffu, s, o);
        if (threadIdx.x == 0) g_part[bid] = s;
    }
}

// ---------------------------------------------------------------------------
// Epilogue (R10 structure — best measured): 1 block, 896 threads.
// Pre-sync (PDL-overlapped): w1 -> smem, L2 prefetch w2/wc, LN params.
// Post-sync: g_part -> smem, assembly, LN chain, 3 smem matmul stages.
// Smem row strides: 113 f4 (448-f rows), 17 f4 (64-f rows) -> conflict-free.
// x2 assembly reads stride-25 floats: gcd(25,32)=1 -> conflict-free.
// ---------------------------------------------------------------------------

extern __shared__ float4 dynw[];     // 7616 float4 = 121856 B

__device__ __forceinline__ float2 gsum2(float a, float b, float* sbuf)
{
    #pragma unroll
    for (int o = 16; o; o >>= 1) {
        a += __shfl_down_sync(0xffffffffu, a, o);
        b += __shfl_down_sync(0xffffffffu, b, o);
    }
    int w = threadIdx.x >> 5;
    int lane = threadIdx.x & 31;
    if (lane == 0) { sbuf[w] = a; sbuf[32 + w] = b; }
    __syncthreads();
    if (w == 0 || w == 14) {
        float x = (lane < 14) ? sbuf[w + lane]      : 0.f;
        float y = (lane < 14) ? sbuf[32 + w + lane] : 0.f;
        #pragma unroll
        for (int o = 16; o; o >>= 1) {
            x += __shfl_down_sync(0xffffffffu, x, o);
            y += __shfl_down_sync(0xffffffffu, y, o);
        }
        if (lane == 0) { sbuf[w] = x; sbuf[32 + w] = y; }
    }
    __syncthreads();
    int base = (threadIdx.x >= 448) ? 14 : 0;
    float2 r = make_float2(sbuf[base], sbuf[32 + base]);
    __syncthreads();
    return r;
}

__device__ __forceinline__ void ln_s(float* v, int n, int t,
                                     const float* w, const float* b,
                                     float* sbuf)
{
    float x  = (t < n) ? v[t] : 0.f;
    float2 s = gsum2(x, x * x, sbuf);
    float inv_n = 1.f / (float)n;
    float mu  = s.x * inv_n;
    float var = fmaxf(s.y * inv_n - mu * mu, 0.f);
    float r   = rsqrtf(var + 1e-5f);
    if (t < n) v[t] = (x - mu) * r * w[t] + b[t];
    __syncthreads();
}

__global__ __launch_bounds__(896) void epilogue(
    const float* __restrict__ ln1w, const float* __restrict__ ln1b,
    const float* __restrict__ ln2w, const float* __restrict__ ln2b,
    const float* __restrict__ ln3w, const float* __restrict__ ln3b,
    const float* __restrict__ ln4w, const float* __restrict__ ln4b,
    const float* __restrict__ ln5w, const float* __restrict__ ln5b,
    const float* __restrict__ mlp_w1, const float* __restrict__ mlp_b1,
    const float* __restrict__ mlp_w2, const float* __restrict__ mlp_b2,
    const float* __restrict__ conv_w, const float* __restrict__ conv_b,
    float* __restrict__ out)
{
    __shared__ __align__(16) float sv[2][448];   // LN workspace / h2
    __shared__ __align__(16) float h1s[2][64];
    __shared__ __align__(16) float red[2][448];
    __shared__ __align__(16) float s_g[4736];    // staged g_part
    __shared__ float sbuf[64];
    __shared__ float s_w[1280];   // ln1@0 ln2@64 ln3@192 ln4@448 ln5@832
    __shared__ float s_b[1280];
    __shared__ float s_b1[64];
    __shared__ float s_b2[448];
    __shared__ float s_bc[64];

    int tid = threadIdx.x;

    // ================= PRE-SYNC (overlaps the streaming tail) =============
    {
        const char* w2c = (const char*)mlp_w2;
        const char* wcc = (const char*)conv_w;
        size_t off = (size_t)tid * 128;
        asm volatile("prefetch.global.L2 [%0];" :: "l"(w2c + off));
        asm volatile("prefetch.global.L2 [%0];" :: "l"(wcc + off));
    }
    {
        const float4* g4 = reinterpret_cast<const float4*>(mlp_w1);
        #pragma unroll
        for (int v = tid; v < 7168; v += 896) {
            int row = v / 112;           // 112 float4 per 448-float row
            int col = v - row * 112;
            dynw[row * 113 + col] = g4[v];
        }
    }
    if (tid < 64)   { s_w[tid]       = ln1w[tid]; s_b[tid]       = ln1b[tid]; }
    if (tid < 128)  { s_w[64 + tid]  = ln2w[tid]; s_b[64 + tid]  = ln2b[tid]; }
    if (tid < 256)  { s_w[192 + tid] = ln3w[tid]; s_b[192 + tid] = ln3b[tid]; }
    if (tid < 384)  { s_w[448 + tid] = ln4w[tid]; s_b[448 + tid] = ln4b[tid]; }
    if (tid < 448)  { s_w[832 + tid] = ln5w[tid]; s_b[832 + tid] = ln5b[tid]; }
    if (tid < 64)   s_b1[tid] = mlp_b1[tid];
    if (tid < 448)  s_b2[tid] = mlp_b2[tid];
    if (tid >= 448 && tid < 512) s_bc[tid - 448] = conv_b[tid - 448];

    // ================= WAIT for gap_reduce completion ======================
#if __CUDA_ARCH__ >= 900
    cudaGridDependencySynchronize();
#endif
    __syncthreads();

    // --- Stage g_part into smem, fully coalesced (1184 float4) ---
    {
        const float4* gp4 = reinterpret_cast<const float4*>(g_part);
        float4* sg4 = reinterpret_cast<float4*>(s_g);
        #pragma unroll
        for (int v = tid; v < 1184; v += 896) sg4[v] = gp4[v];
    }
    __syncthreads();

    int b = tid / 448;
    int t = tid - b * 448;
    float* svb = sv[b];

    // --- Assemble raw GAP means from smem ---
    if (t < 64) {                    // x2: stride-25 reads, conflict-free
        int base = (b * 64 + t) * 25;
        float s = 0.f;
        #pragma unroll
        for (int k = 0; k < 25; k++) s += s_g[base + k];
        svb[t] = s * (1.f / 2097152.f);
    }
    if (t < 128) {
        int base = 3200 + (b * 128 + t) * 4;
        float s = 0.f;
        #pragma unroll
        for (int k = 0; k < 4; k++) s += s_g[base + k];
        svb[64 + t] = s * (1.f / 262144.f);
    }
    if (t < 256) {
        svb[192 + t] = s_g[4224 + b * 256 + t] * (1.f / 32768.f);
    }
    __syncthreads();

    // --- LayerNorm chain ---
    ln_s(svb,        64, t, s_w,       s_b,       sbuf);
    ln_s(svb +  64, 128, t, s_w + 64,  s_b + 64,  sbuf);
    ln_s(svb + 192, 256, t, s_w + 192, s_b + 192, sbuf);
    ln_s(svb +  64, 384, t, s_w + 448, s_b + 448, sbuf);
    ln_s(svb,       448, t, s_w + 832, s_b + 832, sbuf);

    int c = t >> 6;                   // chunk 0..6
    int o = t & 63;                   // output 0..63

    // ======================= Stage 1: W1 dot from smem =====================
    {
        const float4* wr = dynw + o * 113 + c * 16;
        const float4* xr = reinterpret_cast<const float4*>(svb + c * 64);
        float p = 0.f;
        #pragma unroll
        for (int k = 0; k < 16; k++) {
            float4 wv = wr[k], xv = xr[k];
            p = fmaf(wv.x, xv.x, p); p = fmaf(wv.y, xv.y, p);
            p = fmaf(wv.z, xv.z, p); p = fmaf(wv.w, xv.w, p);
        }
        red[b][t] = p;
    }
    __syncthreads();
    if (tid < 128) {
        int bb = tid >> 6, oo = tid & 63;
        float acc = s_b1[oo];
        #pragma unroll
        for (int cc = 0; cc < 7; cc++) acc += red[bb][cc * 64 + oo];
        h1s[bb][oo] = fmaxf(acc, 0.f);
    }
    __syncthreads();

    // ============== Stage 2: copy w2 (L2-hot) -> smem, dot ================
    {
        const float4* g4 = reinterpret_cast<const float4*>(mlp_w2);
        #pragma unroll
        for (int v = tid; v < 7168; v += 896) {
            int row = v >> 4;            // 16 float4 per 64-float row
            int col = v & 15;
            dynw[row * 17 + col] = g4[v];
        }
    }
    __syncthreads();
    {
        const float4* wr = dynw + t * 17;            // row jj = t
        const float4* hr = reinterpret_cast<const float4*>(h1s[b]);
        float acc = s_b2[t];
        #pragma unroll
        for (int k = 0; k < 16; k++) {
            float4 wv = wr[k], hv = hr[k];
            acc = fmaf(wv.x, hv.x, acc); acc = fmaf(wv.y, hv.y, acc);
            acc = fmaf(wv.z, hv.z, acc); acc = fmaf(wv.w, hv.w, acc);
        }
        acc = fmaxf(acc, 0.f);
        __syncthreads();              // all stage-2 smem reads done
        svb[t] = acc;                 // h2 -> sv
    }
    __syncthreads();

    // ============== Stage 3: copy conv_w (L2-hot) -> smem, dot ============
    {
        const float4* g4 = reinterpret_cast<const float4*>(conv_w);
        #pragma unroll
        for (int v = tid; v < 7168; v += 896) {
            int row = v / 112;
            int col = v - row * 112;
            dynw[row * 113 + col] = g4[v];
        }
    }
    __syncthreads();
    {
        const float4* wr = dynw + o * 113 + c * 16;
        const float4* xr = reinterpret_cast<const float4*>(svb + c * 64);
        float p = 0.f;
        #pragma unroll
        for (int k = 0; k < 16; k++) {
            float4 wv = wr[k], xv = xr[k];
            p = fmaf(wv.x, xv.x, p); p = fmaf(wv.y, xv.y, p);
            p = fmaf(wv.z, xv.z, p); p = fmaf(wv.w, xv.w, p);
        }
        red[b][t] = p;
    }
    __syncthreads();
    if (tid < 128) {
        int bb = tid >> 6, oo = tid & 63;
        float acc = s_bc[oo];
        #pragma unroll
        for (int cc = 0; cc < 7; cc++) acc += red[bb][cc * 64 + oo];
        out[bb * 64 + oo] = 1.f / (1.f + expf(-acc));
    }
}

// ---------------------------------------------------------------------------

extern "C" void kernel_launch(void* const* d_in, const int* in_sizes, int n_in,
                              void* d_out, int out_size)
{
    const float* x0 = (const float*)d_in[0];
    const float* x1 = (const float*)d_in[1];
    const float* x2 = (const float*)d_in[2];

    gap_reduce<<<4736, 256>>>(x0, x1, x2);

    const int dyn_bytes = 7616 * 16;   // 121856 B
    static int attr_set = 0;
    if (!attr_set) {
        cudaFuncSetAttribute(epilogue,
                             cudaFuncAttributeMaxDynamicSharedMemorySize,
                             dyn_bytes);
        attr_set = 1;
    }

    cudaLaunchConfig_t cfg = {};
    cfg.gridDim  = dim3(1, 1, 1);
    cfg.blockDim = dim3(896, 1, 1);
    cfg.dynamicSmemBytes = dyn_bytes;
    cudaLaunchAttribute attrs[1];
    attrs[0].id = cudaLaunchAttributeProgrammaticStreamSerialization;
    attrs[0].val.programmaticStreamSerializationAllowed = 1;
    cfg.attrs = attrs;
    cfg.numAttrs = 1;

    cudaLaunchKernelEx(&cfg, epilogue,
        (const float*)d_in[3],  (const float*)d_in[4],
        (const float*)d_in[5],  (const float*)d_in[6],
        (const float*)d_in[7],  (const float*)d_in[8],
        (const float*)d_in[9],  (const float*)d_in[10],
        (const float*)d_in[11], (const float*)d_in[12],
        (const float*)d_in[13], (const float*)d_in[14],
        (const float*)d_in[15], (const float*)d_in[16],
        (const float*)d_in[17], (const float*)d_in[18],
        (float*)d_out);
}

// round 14
// speedup vs baseline: 1.0288x; 1.0288x over previous
#include <cuda_runtime.h>
#include <cstdint>
#include <math.h>

// ---------------------------------------------------------------------------
// FINAL (R10 configuration — best measured: 203.8 us)
// Shapes
//   x0: [2, 256, 32^3]   -> 512 channel-slices of 32768 elems
//   x1: [2, 128, 64^3]   -> 256 channel-slices of 262144 elems
//   x2: [2,  64, 128^3]  -> 128 channel-slices of 2097152 elems
// Partial-sum layout (deterministic, no atomics):
//   x2: 32 partials/slice -> 4096 at g_part[0]
//   x1:  4 partials/slice -> 1024 at g_part[4096]
//   x0:  1 partial/slice  ->  512 at g_part[5120]
// gap_reduce fires PDL completion at entry; the epilogue is launched with
// PSS so its weight staging overlaps the stream tail, and
// cudaGridDependencySynchronize() gates the g_part reads.
// ---------------------------------------------------------------------------

__device__ __align__(16) float g_part[5632];

__global__ __launch_bounds__(256) void gap_reduce(
    const float* __restrict__ x0,
    const float* __restrict__ x1,
    const float* __restrict__ x2)
{
#if __CUDA_ARCH__ >= 900
    cudaTriggerProgrammaticLaunchCompletion();
#endif
    int bid = blockIdx.x;

    const float4* src;
    int nvec;
    if (bid < 4096) {
        src  = reinterpret_cast<const float4*>(x2) + (size_t)bid * 16384;
        nvec = 16384;
    } else if (bid < 5120) {
        src  = reinterpret_cast<const float4*>(x1) + (size_t)(bid - 4096) * 16384;
        nvec = 16384;
    } else {
        src  = reinterpret_cast<const float4*>(x0) + (size_t)(bid - 5120) * 8192;
        nvec = 8192;
    }

    float s = 0.f;
    #pragma unroll 4
    for (int i = threadIdx.x; i < nvec; i += 256) {
        float4 a = __ldcs(src + i);          // streaming: evict-first in L2
        s += (a.x + a.y) + (a.z + a.w);
    }

    __shared__ float sbuf[8];
    #pragma unroll
    for (int o = 16; o; o >>= 1) s += __shfl_down_sync(0xffffffffu, s, o);
    if ((threadIdx.x & 31) == 0) sbuf[threadIdx.x >> 5] = s;
    __syncthreads();
    if (threadIdx.x < 8) {
        s = sbuf[threadIdx.x];
        #pragma unroll
        for (int o = 4; o; o >>= 1) s += __shfl_down_sync(0x000000ffu, s, o);
        if (threadIdx.x == 0) g_part[bid] = s;
    }
}

// ---------------------------------------------------------------------------
// Epilogue: 1 block, 896 threads (warps 0-13 batch0, 14-27 batch1).
// Pre-sync (overlapped with the stream tail via PDL): w1 -> smem, L2
// prefetch of w2/wc, LN params -> smem. Post-sync: g_part -> smem
// (coalesced), assembly (rotated banks), LN chain, 3 smem matmul stages.
// Smem row strides: 113 float4 (448-f rows), 17 float4 (64-f rows)
// -> stride mod 128B == 16B -> conflict-free LDS.128 phases.
// ---------------------------------------------------------------------------

extern __shared__ float4 dynw[];     // 7616 float4 = 121856 B

__device__ __forceinline__ float2 gsum2(float a, float b, float* sbuf)
{
    #pragma unroll
    for (int o = 16; o; o >>= 1) {
        a += __shfl_down_sync(0xffffffffu, a, o);
        b += __shfl_down_sync(0xffffffffu, b, o);
    }
    int w = threadIdx.x >> 5;
    int lane = threadIdx.x & 31;
    if (lane == 0) { sbuf[w] = a; sbuf[32 + w] = b; }
    __syncthreads();
    if (w == 0 || w == 14) {
        float x = (lane < 14) ? sbuf[w + lane]      : 0.f;
        float y = (lane < 14) ? sbuf[32 + w + lane] : 0.f;
        #pragma unroll
        for (int o = 16; o; o >>= 1) {
            x += __shfl_down_sync(0xffffffffu, x, o);
            y += __shfl_down_sync(0xffffffffu, y, o);
        }
        if (lane == 0) { sbuf[w] = x; sbuf[32 + w] = y; }
    }
    __syncthreads();
    int base = (threadIdx.x >= 448) ? 14 : 0;
    float2 r = make_float2(sbuf[base], sbuf[32 + base]);
    __syncthreads();
    return r;
}

__device__ __forceinline__ void ln_s(float* v, int n, int t,
                                     const float* w, const float* b,
                                     float* sbuf)
{
    float x  = (t < n) ? v[t] : 0.f;
    float2 s = gsum2(x, x * x, sbuf);
    float inv_n = 1.f / (float)n;
    float mu  = s.x * inv_n;
    float var = fmaxf(s.y * inv_n - mu * mu, 0.f);
    float r   = rsqrtf(var + 1e-5f);
    if (t < n) v[t] = (x - mu) * r * w[t] + b[t];
    __syncthreads();
}

__global__ __launch_bounds__(896) void epilogue(
    const float* __restrict__ ln1w, const float* __restrict__ ln1b,
    const float* __restrict__ ln2w, const float* __restrict__ ln2b,
    const float* __restrict__ ln3w, const float* __restrict__ ln3b,
    const float* __restrict__ ln4w, const float* __restrict__ ln4b,
    const float* __restrict__ ln5w, const float* __restrict__ ln5b,
    const float* __restrict__ mlp_w1, const float* __restrict__ mlp_b1,
    const float* __restrict__ mlp_w2, const float* __restrict__ mlp_b2,
    const float* __restrict__ conv_w, const float* __restrict__ conv_b,
    float* __restrict__ out)
{
    __shared__ __align__(16) float sv[2][448];   // LN workspace / h2
    __shared__ __align__(16) float h1s[2][64];
    __shared__ __align__(16) float red[2][448];
    __shared__ __align__(16) float s_g[5632];    // staged g_part
    __shared__ float sbuf[64];
    __shared__ float s_w[1280];   // ln1@0 ln2@64 ln3@192 ln4@448 ln5@832
    __shared__ float s_b[1280];
    __shared__ float s_b1[64];
    __shared__ float s_b2[448];
    __shared__ float s_bc[64];

    int tid = threadIdx.x;

    // ================= PRE-SYNC (overlaps the streaming tail) =============
    {
        const char* w2c = (const char*)mlp_w2;
        const char* wcc = (const char*)conv_w;
        size_t off = (size_t)tid * 128;
        asm volatile("prefetch.global.L2 [%0];" :: "l"(w2c + off));
        asm volatile("prefetch.global.L2 [%0];" :: "l"(wcc + off));
    }
    {
        const float4* g4 = reinterpret_cast<const float4*>(mlp_w1);
        #pragma unroll
        for (int v = tid; v < 7168; v += 896) {
            int row = v / 112;           // 112 float4 per 448-float row
            int col = v - row * 112;
            dynw[row * 113 + col] = g4[v];
        }
    }
    if (tid < 64)   { s_w[tid]       = ln1w[tid]; s_b[tid]       = ln1b[tid]; }
    if (tid < 128)  { s_w[64 + tid]  = ln2w[tid]; s_b[64 + tid]  = ln2b[tid]; }
    if (tid < 256)  { s_w[192 + tid] = ln3w[tid]; s_b[192 + tid] = ln3b[tid]; }
    if (tid < 384)  { s_w[448 + tid] = ln4w[tid]; s_b[448 + tid] = ln4b[tid]; }
    if (tid < 448)  { s_w[832 + tid] = ln5w[tid]; s_b[832 + tid] = ln5b[tid]; }
    if (tid < 64)   s_b1[tid] = mlp_b1[tid];
    if (tid < 448)  s_b2[tid] = mlp_b2[tid];
    if (tid >= 448 && tid < 512) s_bc[tid - 448] = conv_b[tid - 448];

    // ================= WAIT for gap_reduce completion ======================
#if __CUDA_ARCH__ >= 900
    cudaGridDependencySynchronize();
#endif
    __syncthreads();

    // --- Stage g_part into smem, fully coalesced (1408 float4) ---
    {
        const float4* gp4 = reinterpret_cast<const float4*>(g_part);
        float4* sg4 = reinterpret_cast<float4*>(s_g);
        #pragma unroll
        for (int v = tid; v < 1408; v += 896) sg4[v] = gp4[v];
    }
    __syncthreads();

    int b = tid / 448;
    int t = tid - b * 448;
    float* svb = sv[b];

    // --- Assemble raw GAP means from smem ---
    if (t < 64) {                    // x2: rotated index -> conflict-free
        int base = (b * 64 + t) * 32;
        float s = 0.f;
        #pragma unroll
        for (int k = 0; k < 32; k++) s += s_g[base + ((k + t) & 31)];
        svb[t] = s * (1.f / 2097152.f);
    }
    if (t < 128) {
        int base = 4096 + (b * 128 + t) * 4;
        float s = 0.f;
        #pragma unroll
        for (int k = 0; k < 4; k++) s += s_g[base + k];
        svb[64 + t] = s * (1.f / 262144.f);
    }
    if (t < 256) {
        svb[192 + t] = s_g[5120 + b * 256 + t] * (1.f / 32768.f);
    }
    __syncthreads();

    // --- LayerNorm chain ---
    ln_s(svb,        64, t, s_w,       s_b,       sbuf);
    ln_s(svb +  64, 128, t, s_w + 64,  s_b + 64,  sbuf);
    ln_s(svb + 192, 256, t, s_w + 192, s_b + 192, sbuf);
    ln_s(svb +  64, 384, t, s_w + 448, s_b + 448, sbuf);
    ln_s(svb,       448, t, s_w + 832, s_b + 832, sbuf);

    int c = t >> 6;                   // chunk 0..6
    int o = t & 63;                   // output 0..63

    // =======================================================================
    // Stage 1: partial dot over chunk c of row o, weights from smem.
    // =======================================================================
    {
        const float4* wr = dynw + o * 113 + c * 16;
        const float4* xr = reinterpret_cast<const float4*>(svb + c * 64);
        float p = 0.f;
        #pragma unroll
        for (int k = 0; k < 16; k++) {
            float4 wv = wr[k], xv = xr[k];
            p = fmaf(wv.x, xv.x, p); p = fmaf(wv.y, xv.y, p);
            p = fmaf(wv.z, xv.z, p); p = fmaf(wv.w, xv.w, p);
        }
        red[b][t] = p;
    }
    __syncthreads();
    if (tid < 128) {
        int bb = tid >> 6, oo = tid & 63;
        float acc = s_b1[oo];
        #pragma unroll
        for (int cc = 0; cc < 7; cc++) acc += red[bb][cc * 64 + oo];
        h1s[bb][oo] = fmaxf(acc, 0.f);
    }
    __syncthreads();

    // =======================================================================
    // Stage 2: copy w2 (448x64, L2-hot) into smem (17-f4 stride), then
    // thread-per-(b,jj) dot of 64 from smem.
    // =======================================================================
    {
        const float4* g4 = reinterpret_cast<const float4*>(mlp_w2);
        #pragma unroll
        for (int v = tid; v < 7168; v += 896) {
            int row = v >> 4;            // 16 float4 per 64-float row
            int col = v & 15;
            dynw[row * 17 + col] = g4[v];
        }
    }
    __syncthreads();
    {
        const float4* wr = dynw + t * 17;            // row jj = t
        const float4* hr = reinterpret_cast<const float4*>(h1s[b]);
        float acc = s_b2[t];
        #pragma unroll
        for (int k = 0; k < 16; k++) {
            float4 wv = wr[k], hv = hr[k];
            acc = fmaf(wv.x, hv.x, acc); acc = fmaf(wv.y, hv.y, acc);
            acc = fmaf(wv.z, hv.z, acc); acc = fmaf(wv.w, hv.w, acc);
        }
        acc = fmaxf(acc, 0.f);
        __syncthreads();              // all stage-2 smem reads done
        svb[t] = acc;                 // h2 -> sv
    }
    __syncthreads();

    // =======================================================================
    // Stage 3: copy conv_w (L2-hot), chunk-dot, sigmoid finish.
    // =======================================================================
    {
        const float4* g4 = reinterpret_cast<const float4*>(conv_w);
        #pragma unroll
        for (int v = tid; v < 7168; v += 896) {
            int row = v / 112;
            int col = v - row * 112;
            dynw[row * 113 + col] = g4[v];
        }
    }
    __syncthreads();
    {
        const float4* wr = dynw + o * 113 + c * 16;
        const float4* xr = reinterpret_cast<const float4*>(svb + c * 64);
        float p = 0.f;
        #pragma unroll
        for (int k = 0; k < 16; k++) {
            float4 wv = wr[k], xv = xr[k];
            p = fmaf(wv.x, xv.x, p); p = fmaf(wv.y, xv.y, p);
            p = fmaf(wv.z, xv.z, p); p = fmaf(wv.w, xv.w, p);
        }
        red[b][t] = p;
    }
    __syncthreads();
    if (tid < 128) {
        int bb = tid >> 6, oo = tid & 63;
        float acc = s_bc[oo];
        #pragma unroll
        for (int cc = 0; cc < 7; cc++) acc += red[bb][cc * 64 + oo];
        out[bb * 64 + oo] = 1.f / (1.f + expf(-acc));
    }
}

// ---------------------------------------------------------------------------

extern "C" void kernel_launch(void* const* d_in, const int* in_sizes, int n_in,
                              void* d_out, int out_size)
{
    const float* x0 = (const float*)d_in[0];
    const float* x1 = (const float*)d_in[1];
    const float* x2 = (const float*)d_in[2];

    gap_reduce<<<5632, 256>>>(x0, x1, x2);

    const int dyn_bytes = 7616 * 16;   // 121856 B
    static int attr_set = 0;
    if (!attr_set) {
        cudaFuncSetAttribute(epilogue,
                             cudaFuncAttributeMaxDynamicSharedMemorySize,
                             dyn_bytes);
        attr_set = 1;
    }

    cudaLaunchConfig_t cfg = {};
    cfg.gridDim  = dim3(1, 1, 1);
    cfg.blockDim = dim3(896, 1, 1);
    cfg.dynamicSmemBytes = dyn_bytes;
    cudaLaunchAttribute attrs[1];
    attrs[0].id = cudaLaunchAttributeProgrammaticStreamSerialization;
    attrs[0].val.programmaticStreamSerializationAllowed = 1;
    cfg.attrs = attrs;
    cfg.numAttrs = 1;

    cudaLaunchKernelEx(&cfg, epilogue,
        (const float*)d_in[3],  (const float*)d_in[4],
        (const float*)d_in[5],  (const float*)d_in[6],
        (const float*)d_in[7],  (const float*)d_in[8],
        (const float*)d_in[9],  (const float*)d_in[10],
        (const float*)d_in[11], (const float*)d_in[12],
        (const float*)d_in[13], (const float*)d_in[14],
        (const float*)d_in[15], (const float*)d_in[16],
        (const float*)d_in[17], (const float*)d_in[18],
        (float*)d_out);
}